// round 15
// baseline (speedup 1.0000x reference)
#include <cuda_runtime.h>
#include <cuda_fp16.h>
#include <cstdint>

// out[i,j] = sigmoid( sum_h W2[h]*relu(A[i,h]+B[j,h]) + b2 )
//   A = Z@W1[:D] + b1, B = Z@W1[D:].
// Identity: relu(a+b) = max(a,-b)+b  =>  logits = sum_h w*max(a,-b) + C_j + b2.
// N^2-scale sum in packed f16x2 (HMNMX2 + HFMA2 = 1 slot/pair-h, pipes 1:1);
// C_j correction + final reduce in fp32. Two half2 accumulators per pair
// (h<32 / h>=32) bound fp16 accumulation error.
#define NN 2048
#define DD 32
#define HH 64

__device__ __half g_Ah [NN * HH];  // A[n][h]   (fp16)
__device__ __half g_nBh[NN * HH];  // -B[n][h]  (fp16)
__device__ float  g_C  [NN];       // C[j] = sum_h W2[h]*B[j,h]  (fp32)
__device__ int    g_ctr;           // work-stealing tile counter

// acc(h2) += max.f16x2(a,b)*w twice (two h-pairs).
__device__ __forceinline__ void hmax_fma(unsigned& acc,
                                         unsigned alo, unsigned ahi,
                                         unsigned blo, unsigned bhi,
                                         unsigned wlo, unsigned whi) {
    asm("{\n\t"
        ".reg .b32 t0, t1;\n\t"
        "max.f16x2 t0, %1, %3;\n\t"
        "max.f16x2 t1, %2, %4;\n\t"
        "fma.rn.f16x2 %0, t0, %5, %0;\n\t"
        "fma.rn.f16x2 %0, t1, %6, %0;\n\t"
        "}" : "+r"(acc)
            : "r"(alo), "r"(ahi), "r"(blo), "r"(bhi), "r"(wlo), "r"(whi));
}

__device__ __forceinline__ void cp8(void* s, const void* g) {
    unsigned int sa = (unsigned int)__cvta_generic_to_shared(s);
    asm volatile("cp.async.ca.shared.global [%0], [%1], 8;" :: "r"(sa), "l"(g));
}

#define GRID 592   // 4 CTAs/SM x 148 SMs

// ---------------------------------------------------------------------------
// Prep: fp16 A and -B, fp32 C, reset counter. 512 blocks x 256 threads.
// ---------------------------------------------------------------------------
__global__ void prep_kernel(const float* __restrict__ Z,
                            const float* __restrict__ W1,
                            const float* __restrict__ b1,
                            const float* __restrict__ W2) {
    __shared__ float zs[4][DD];
    __shared__ float cbuf[4][HH];
    int tid = threadIdx.x;
    int nblk = blockIdx.x * 4;
    if (blockIdx.x == 0 && tid == 0) g_ctr = GRID;
    if (tid < 4 * DD) {
        zs[tid >> 5][tid & 31] = Z[(nblk + (tid >> 5)) * DD + (tid & 31)];
    }
    __syncthreads();
    int local_n = tid >> 6;
    int h = tid & 63;
    int n = nblk + local_n;
    float sa = b1[h];
    float sb = 0.0f;
#pragma unroll
    for (int d = 0; d < DD; d++) {
        float z = zs[local_n][d];
        sa = fmaf(z, W1[d * HH + h], sa);
        sb = fmaf(z, W1[(DD + d) * HH + h], sb);
    }
    g_Ah [n * HH + h] = __float2half_rn(sa);
    g_nBh[n * HH + h] = __float2half_rn(-sb);
    cbuf[local_n][h] = sb * W2[h];     // fp32 correction term
    __syncthreads();
    if (tid < 4) {
        float c = 0.0f;
#pragma unroll
        for (int k = 0; k < HH; k++) c += cbuf[tid][k];
        g_C[nblk + tid] = c;
    }
}

// ---------------------------------------------------------------------------
// Persistent pair kernel: 4 CTAs/SM (32 warps — cross-warp latency hiding
// replaces the register ping-pong), work-stealing, cp.async double-buffered
// fp16 tiles, point-of-use batched loads per fully-unrolled 4h-step.
// 64x64 tile, 4x4 pairs/thread, interleaved lanes (i=ty+16*ii, j=tx+16*jj).
// SROWH=68 halves (136B row): conflict-free 8B loads.
// ---------------------------------------------------------------------------
#define SROWH 68
#define HBUF (64 * SROWH)
#define NTILES 1024

__device__ __forceinline__ float sigmoid_fast(float x) {
    float t;
    asm("tanh.approx.f32 %0, %1;" : "=f"(t) : "f"(0.5f * x));
    return fmaf(0.5f, t, 0.5f);
}

__global__ __launch_bounds__(256, 4)
void pair_kernel(const float* __restrict__ W2,
                 const float* __restrict__ b2,
                 float* __restrict__ out) {
    extern __shared__ __half hs[];
    // layout (halves): A0 | A1 | B0 | B1 | ws(72) | next_t(int)
    __half* ws = hs + 4 * HBUF;
    int* next_s = (int*)(ws + 72);

    int tid = threadIdx.x;
    int tx = tid & 15;   // j lane
    int ty = tid >> 4;   // i lane
    float bias = b2[0];

    if (tid < HH) ws[tid] = __float2half_rn(W2[tid]);
    if (tid >= 64 && tid < 72) ws[tid] = __ushort_as_half((unsigned short)0);

    int t = blockIdx.x;
    int p = 0;
    {   // Prologue: stage tile t into buffer 0
        int bj = (t & 31) * 64, bi = (t >> 5) * 64;
        const __half* gA = g_Ah  + bi * HH;
        const __half* gB = g_nBh + bj * HH;
        for (int k = tid; k < 1024; k += 256) {
            int row = k >> 4, ch = (k & 15) * 4;
            cp8(hs + row * SROWH + ch,            gA + row * HH + ch);
            cp8(hs + 2 * HBUF + row * SROWH + ch, gB + row * HH + ch);
        }
        asm volatile("cp.async.commit_group;");
    }

    while (true) {
        if (tid == 0) *next_s = atomicAdd(&g_ctr, 1);
        __syncthreads();               // prev compute on buf p^1 done; next_s visible
        int tn = *next_s;
        if (tn < NTILES) {
            int bj = (tn & 31) * 64, bi = (tn >> 5) * 64;
            const __half* gA = g_Ah  + bi * HH;
            const __half* gB = g_nBh + bj * HH;
            __half* sA = hs + (p ^ 1) * HBUF;
            __half* sB = hs + (2 + (p ^ 1)) * HBUF;
            for (int k = tid; k < 1024; k += 256) {
                int row = k >> 4, ch = (k & 15) * 4;
                cp8(sA + row * SROWH + ch, gA + row * HH + ch);
                cp8(sB + row * SROWH + ch, gB + row * HH + ch);
            }
        }
        asm volatile("cp.async.commit_group;");
        asm volatile("cp.async.wait_group 1;");   // buf p arrived
        __syncthreads();

        int bj = (t & 31) * 64, bi = (t >> 5) * 64;
        const __half* ar = hs + p * HBUF + ty * SROWH;
        const __half* br = hs + (2 + p) * HBUF + tx * SROWH;

        // two half2 accumulators per pair: window 0 (h<32), window 1 (h>=32)
        unsigned acc[2][4][4];
#pragma unroll
        for (int w = 0; w < 2; w++)
#pragma unroll
            for (int ii = 0; ii < 4; ii++)
#pragma unroll
                for (int jj = 0; jj < 4; jj++) acc[w][ii][jj] = 0u;

        // 16 fully-unrolled 4h-steps; loads batched at step top; no ping-pong
        // (cross-warp hiding at 8 warps/SMSP). Window select is compile-time.
#pragma unroll
        for (int hb = 0; hb < 64; hb += 4) {
            const int wsel = (hb >= 32) ? 1 : 0;
            uint2 wv = *(const uint2*)(ws + hb);
            uint2 av[4], bv[4];
#pragma unroll
            for (int ii = 0; ii < 4; ii++)
                av[ii] = *(const uint2*)(ar + ii * 16 * SROWH + hb);
#pragma unroll
            for (int jj = 0; jj < 4; jj++)
                bv[jj] = *(const uint2*)(br + jj * 16 * SROWH + hb);
#pragma unroll
            for (int jj = 0; jj < 4; jj++)
#pragma unroll
                for (int ii = 0; ii < 4; ii++)
                    hmax_fma(acc[wsel][ii][jj], av[ii].x, av[ii].y,
                             bv[jj].x, bv[jj].y, wv.x, wv.y);
        }

        // epilogue: fp32 reduce + fp32 correction + sigmoid
#pragma unroll
        for (int ii = 0; ii < 4; ii++) {
            int gi = bi + ty + ii * 16;
#pragma unroll
            for (int jj = 0; jj < 4; jj++) {
                int gj = bj + tx + jj * 16;
                float2 u = __half22float2(*(const half2*)&acc[0][ii][jj]);
                float2 v = __half22float2(*(const half2*)&acc[1][ii][jj]);
                float x = (u.x + u.y) + (v.x + v.y) + __ldg(&g_C[gj]) + bias;
                out[gi * NN + gj] = sigmoid_fast(x);   // coalesced across tx
            }
        }

        if (tn >= NTILES) break;
        t = tn;
        p ^= 1;
    }
}

extern "C" void kernel_launch(void* const* d_in, const int* in_sizes, int n_in,
                              void* d_out, int out_size) {
    const float* Z  = (const float*)d_in[0];
    const float* W1 = (const float*)d_in[1];
    const float* b1 = (const float*)d_in[2];
    const float* W2 = (const float*)d_in[3];
    const float* b2 = (const float*)d_in[4];
    float* out = (float*)d_out;

    static const size_t SMEM_BYTES = (4 * HBUF + 72) * sizeof(__half) + 8;
    cudaFuncSetAttribute(pair_kernel,
                         cudaFuncAttributeMaxDynamicSharedMemorySize,
                         (int)SMEM_BYTES);

    prep_kernel<<<NN / 4, 256>>>(Z, W1, b1, W2);
    pair_kernel<<<GRID, 256, SMEM_BYTES>>>(W2, b2, out);
}

// round 16
// speedup vs baseline: 1.0168x; 1.0168x over previous
#include <cuda_runtime.h>
#include <cuda_fp16.h>
#include <cstdint>

// out[i,j] = sigmoid( sum_h W2[h]*relu(A[i,h]+B[j,h]) + b2 )
//   A = Z@W1[:D] + b1, B = Z@W1[D:].
// Identity: relu(a+b) = max(a,-b)+b  =>  logits = sum_h w*max(a,-b) + C_j + b2.
// N^2-scale sum in packed f16x2 (HMNMX2 + HFMA2 = 1 slot/pair-h, pipes 1:1);
// C_j correction + final reduce in fp32. SINGLE half2 accumulator per pair
// (64-term fp16 window; error ~2e-4, gate is 1e-3) -> 16 fewer regs, so the
// register-pipelined (ping-pong) loop fits 4 CTAs/SM.
#define NN 2048
#define DD 32
#define HH 64

__device__ __half g_Ah [NN * HH];  // A[n][h]   (fp16)
__device__ __half g_nBh[NN * HH];  // -B[n][h]  (fp16)
__device__ float  g_C  [NN];       // C[j] = sum_h W2[h]*B[j,h]  (fp32)
__device__ int    g_ctr;           // work-stealing tile counter

// acc(h2) += max.f16x2(a,b)*w twice (two h-pairs).
__device__ __forceinline__ void hmax_fma(unsigned& acc,
                                         unsigned alo, unsigned ahi,
                                         unsigned blo, unsigned bhi,
                                         unsigned wlo, unsigned whi) {
    asm("{\n\t"
        ".reg .b32 t0, t1;\n\t"
        "max.f16x2 t0, %1, %3;\n\t"
        "max.f16x2 t1, %2, %4;\n\t"
        "fma.rn.f16x2 %0, t0, %5, %0;\n\t"
        "fma.rn.f16x2 %0, t1, %6, %0;\n\t"
        "}" : "+r"(acc)
            : "r"(alo), "r"(ahi), "r"(blo), "r"(bhi), "r"(wlo), "r"(whi));
}

__device__ __forceinline__ void cp8(void* s, const void* g) {
    unsigned int sa = (unsigned int)__cvta_generic_to_shared(s);
    asm volatile("cp.async.ca.shared.global [%0], [%1], 8;" :: "r"(sa), "l"(g));
}

#define GRID 592   // 4 CTAs/SM x 148 SMs

// ---------------------------------------------------------------------------
// Prep: fp16 A and -B, fp32 C, reset counter. 512 blocks x 256 threads.
// ---------------------------------------------------------------------------
__global__ void prep_kernel(const float* __restrict__ Z,
                            const float* __restrict__ W1,
                            const float* __restrict__ b1,
                            const float* __restrict__ W2) {
    __shared__ float zs[4][DD];
    __shared__ float cbuf[4][HH];
    int tid = threadIdx.x;
    int nblk = blockIdx.x * 4;
    if (blockIdx.x == 0 && tid == 0) g_ctr = GRID;
    if (tid < 4 * DD) {
        zs[tid >> 5][tid & 31] = Z[(nblk + (tid >> 5)) * DD + (tid & 31)];
    }
    __syncthreads();
    int local_n = tid >> 6;
    int h = tid & 63;
    int n = nblk + local_n;
    float sa = b1[h];
    float sb = 0.0f;
#pragma unroll
    for (int d = 0; d < DD; d++) {
        float z = zs[local_n][d];
        sa = fmaf(z, W1[d * HH + h], sa);
        sb = fmaf(z, W1[(DD + d) * HH + h], sb);
    }
    g_Ah [n * HH + h] = __float2half_rn(sa);
    g_nBh[n * HH + h] = __float2half_rn(-sb);
    cbuf[local_n][h] = sb * W2[h];     // fp32 correction term
    __syncthreads();
    if (tid < 4) {
        float c = 0.0f;
#pragma unroll
        for (int k = 0; k < HH; k++) c += cbuf[tid][k];
        g_C[nblk + tid] = c;
    }
}

// ---------------------------------------------------------------------------
// Persistent pair kernel: 4 CTAs/SM AND register ping-pong (single acc window
// freed the regs), work-stealing, cp.async double-buffered fp16 tiles.
// 64x64 tile, 4x4 pairs/thread, interleaved lanes (i=ty+16*ii, j=tx+16*jj).
// SROWH=68 halves (136B row): conflict-free 8B loads.
// ---------------------------------------------------------------------------
#define SROWH 68
#define HBUF (64 * SROWH)
#define NTILES 1024

__device__ __forceinline__ float sigmoid_fast(float x) {
    float t;
    asm("tanh.approx.f32 %0, %1;" : "=f"(t) : "f"(0.5f * x));
    return fmaf(0.5f, t, 0.5f);
}

__global__ __launch_bounds__(256, 4)
void pair_kernel(const float* __restrict__ W2,
                 const float* __restrict__ b2,
                 float* __restrict__ out) {
    extern __shared__ __half hs[];
    // layout (halves): A0 | A1 | B0 | B1 | ws(72) | next_t(int)
    __half* ws = hs + 4 * HBUF;
    int* next_s = (int*)(ws + 72);

    int tid = threadIdx.x;
    int tx = tid & 15;   // j lane
    int ty = tid >> 4;   // i lane
    float bias = b2[0];

    if (tid < HH) ws[tid] = __float2half_rn(W2[tid]);
    if (tid >= 64 && tid < 72) ws[tid] = __ushort_as_half((unsigned short)0);

    int t = blockIdx.x;
    int p = 0;
    {   // Prologue: stage tile t into buffer 0
        int bj = (t & 31) * 64, bi = (t >> 5) * 64;
        const __half* gA = g_Ah  + bi * HH;
        const __half* gB = g_nBh + bj * HH;
        for (int k = tid; k < 1024; k += 256) {
            int row = k >> 4, ch = (k & 15) * 4;
            cp8(hs + row * SROWH + ch,            gA + row * HH + ch);
            cp8(hs + 2 * HBUF + row * SROWH + ch, gB + row * HH + ch);
        }
        asm volatile("cp.async.commit_group;");
    }

    while (true) {
        if (tid == 0) *next_s = atomicAdd(&g_ctr, 1);
        __syncthreads();               // prev compute on buf p^1 done; next_s visible
        int tn = *next_s;
        if (tn < NTILES) {
            int bj = (tn & 31) * 64, bi = (tn >> 5) * 64;
            const __half* gA = g_Ah  + bi * HH;
            const __half* gB = g_nBh + bj * HH;
            __half* sA = hs + (p ^ 1) * HBUF;
            __half* sB = hs + (2 + (p ^ 1)) * HBUF;
            for (int k = tid; k < 1024; k += 256) {
                int row = k >> 4, ch = (k & 15) * 4;
                cp8(sA + row * SROWH + ch, gA + row * HH + ch);
                cp8(sB + row * SROWH + ch, gB + row * HH + ch);
            }
        }
        asm volatile("cp.async.commit_group;");
        asm volatile("cp.async.wait_group 1;");   // buf p arrived
        __syncthreads();

        int bj = (t & 31) * 64, bi = (t >> 5) * 64;
        const __half* ar = hs + p * HBUF + ty * SROWH;
        const __half* br = hs + (2 + p) * HBUF + tx * SROWH;

        // single half2 accumulator per pair
        unsigned acc[4][4];
#pragma unroll
        for (int ii = 0; ii < 4; ii++)
#pragma unroll
            for (int jj = 0; jj < 4; jj++) acc[ii][jj] = 0u;

        // register ping-pong over 16 steps of 4h
        uint2 ax[4], bx[4], wx;
        uint2 ay[4], by[4], wy;

#define LOADB(AV, BV, WV, h)                                                   \
        do {                                                                   \
            WV = *(const uint2*)(ws + (h));                                    \
            _Pragma("unroll")                                                  \
            for (int ii = 0; ii < 4; ii++)                                     \
                AV[ii] = *(const uint2*)(ar + ii * 16 * SROWH + (h));          \
            _Pragma("unroll")                                                  \
            for (int jj = 0; jj < 4; jj++)                                     \
                BV[jj] = *(const uint2*)(br + jj * 16 * SROWH + (h));          \
        } while (0)

#define COMPB(AV, BV, WV)                                                      \
        do {                                                                   \
            _Pragma("unroll")                                                  \
            for (int jj = 0; jj < 4; jj++)                                     \
                _Pragma("unroll")                                              \
                for (int ii = 0; ii < 4; ii++)                                 \
                    hmax_fma(acc[ii][jj], AV[ii].x, AV[ii].y,                  \
                             BV[jj].x, BV[jj].y, WV.x, WV.y);                  \
        } while (0)

        LOADB(ax, bx, wx, 0);
#pragma unroll
        for (int hb = 0; hb < 64; hb += 8) {
            LOADB(ay, by, wy, hb + 4);
            COMPB(ax, bx, wx);
            LOADB(ax, bx, wx, hb + 8);   // hb=56 loads pad (ws/rows padded; dead)
            COMPB(ay, by, wy);
        }
#undef LOADB
#undef COMPB

        // epilogue: fp32 reduce + fp32 correction + sigmoid
#pragma unroll
        for (int ii = 0; ii < 4; ii++) {
            int gi = bi + ty + ii * 16;
#pragma unroll
            for (int jj = 0; jj < 4; jj++) {
                int gj = bj + tx + jj * 16;
                float2 u = __half22float2(*(const half2*)&acc[ii][jj]);
                float x = u.x + u.y + __ldg(&g_C[gj]) + bias;
                out[gi * NN + gj] = sigmoid_fast(x);   // coalesced across tx
            }
        }

        if (tn >= NTILES) break;
        t = tn;
        p ^= 1;
    }
}

extern "C" void kernel_launch(void* const* d_in, const int* in_sizes, int n_in,
                              void* d_out, int out_size) {
    const float* Z  = (const float*)d_in[0];
    const float* W1 = (const float*)d_in[1];
    const float* b1 = (const float*)d_in[2];
    const float* W2 = (const float*)d_in[3];
    const float* b2 = (const float*)d_in[4];
    float* out = (float*)d_out;

    static const size_t SMEM_BYTES = (4 * HBUF + 72) * sizeof(__half) + 8;
    cudaFuncSetAttribute(pair_kernel,
                         cudaFuncAttributeMaxDynamicSharedMemorySize,
                         (int)SMEM_BYTES);

    prep_kernel<<<NN / 4, 256>>>(Z, W1, b1, W2);
    pair_kernel<<<GRID, 256, SMEM_BYTES>>>(W2, b2, out);
}